// round 4
// baseline (speedup 1.0000x reference)
#include <cuda_runtime.h>
#include <cuda_bf16.h>
#include <math.h>

#define B_ 2
#define L_ 2048
#define CM 96
#define CI 192
#define NS 16
#define KG 12
#define DP 128

// ---------------- scratch (device globals, no allocation) ----------------
__device__ float  g_xin[B_*L_*CI];      // [b][l][c] pre-conv
__device__ float  g_z[B_*L_*CI];        // [b][l][c] silu(z)
__device__ float  g_xc[B_*L_*CI];       // [b][l][c] post conv+silu
__device__ float  g_ysum[B_*L_*CI];     // [b][F][c] accumulated y
__device__ float  g_WinT[CM*2*CI];      // [j][o]
__device__ float  g_WoutT[CI*CM];       // [c][m]
__device__ float  g_convWT[27*CI];      // [tap][c]
__device__ int    g_src[KG*L_];         // scan index -> gather spatial pos
__device__ int    g_dst[KG*L_];         // scan index -> scatter flat pos (per reference spec)
__device__ float  g_Dsum[CI];           // sum Ds over dirs {0,1,2,5,6,7,8,11}
__device__ float  g_D3[CI];             // Ds dir3 + dir9
__device__ float  g_D4[CI];             // Ds dir4 + dir10
__device__ float2 g_dtdu[B_*KG*L_*CI];  // [b][k][t][c] {dt, dt*u}
__device__ float4 g_BC[B_*KG*L_*8];     // [b][k][t][j] {B2j,C2j,B2j+1,C2j+1}
__device__ float  g_xd[B_*DP*CI];       // [b][p][t]
__device__ float  g_dtc[B_*DP*CI];      // [b][ch][t]
__device__ float4 g_BCc[B_*CI*8];       // [b][t][j]
__device__ float  g_yc[B_*DP*CI];       // [b][ch][t]

__device__ __forceinline__ float softplusf(float x){
    return (x > 20.f) ? x : log1pf(expf(x));
}
__device__ __forceinline__ float siluf(float x){
    return x / (1.f + __expf(-x));
}

// ---------------- prep: tables, transposes, inits ----------------
__global__ void k_prep(const float* __restrict__ inw, const float* __restrict__ convw,
                       const float* __restrict__ Ds, const float* __restrict__ downb,
                       const float* __restrict__ outw){
    int i0 = blockIdx.x*blockDim.x + threadIdx.x;
    int T  = gridDim.x*blockDim.x;
    for (int i=i0; i<CM*2*CI; i+=T){ int j=i/(2*CI), o=i%(2*CI); g_WinT[i]=inw[o*CM+j]; }
    for (int i=i0; i<CI*CM;   i+=T){ int c=i/CM,     m=i%CM;     g_WoutT[i]=outw[m*CI+c]; }
    for (int i=i0; i<27*CI;   i+=T){ int tap=i/CI,   c=i%CI;     g_convWT[i]=convw[c*27+tap]; }
    for (int i=i0; i<KG*L_;   i+=T){
        int k=i/L_, t=i%L_;
        int tt = (k>=6) ? (L_-1-t) : t;
        int h,w,d,F;
        switch(k%6){
            case 0: h=tt>>7; w=(tt>>3)&15; d=tt&7;  F=(h*16+w)*8+d;  break;
            case 1: h=tt>>7; d=(tt>>4)&7;  w=tt&15; F=(h*16+w)*8+d;  break;
            case 2: w=tt>>7; h=(tt>>3)&15; d=tt&7;  F=(h*16+w)*8+d;  break;
            case 3: w=tt>>7; d=(tt>>4)&7;  h=tt&15; F=d*256+h*16+w;  break;  // ref spec: pm == fwd perm
            case 4: d=tt>>8; h=(tt>>4)&15; w=tt&15; F=w*128+d*16+h;  break;  // ref spec: pm == fwd perm
            default:d=tt>>8; w=(tt>>4)&15; h=tt&15; F=(h*16+w)*8+d;  break;
        }
        g_src[i] = (h*16+w)*8+d;
        g_dst[i] = F;
    }
    for (int i=i0; i<CI; i+=T){
        float sa=0.f, s3=0.f, s4=0.f;
        #pragma unroll
        for (int k=0;k<KG;k++){
            float v = Ds[k*CI+i];
            int km = k%6;
            if (km==3) s3 += v;
            else if (km==4) s4 += v;
            else sa += v;
        }
        g_Dsum[i]=sa; g_D3[i]=s3; g_D4[i]=s4;
    }
    for (int i=i0; i<B_*DP*CI; i+=T){
        int p=(i/CI)%DP;
        g_xd[i]=downb[p];
    }
}

// ---------------- K1: in_proj GEMM, split xin / silu(z) ----------------
__global__ void k1_inproj(const float* __restrict__ x){
    int b  = blockIdx.x >> 7;
    int l0 = (blockIdx.x & 127) << 4;
    __shared__ float xs[16][CM];
    const float* src = x + ((size_t)b*L_ + l0)*CM;
    for (int i=threadIdx.x; i<16*CM; i+=384) ((float*)xs)[i] = src[i];
    __syncthreads();
    int o = threadIdx.x;
    float acc[16];
    #pragma unroll
    for (int i=0;i<16;i++) acc[i]=0.f;
    for (int j=0;j<CM;j++){
        float w = g_WinT[j*(2*CI)+o];
        #pragma unroll
        for (int i=0;i<16;i++) acc[i] = fmaf(w, xs[i][j], acc[i]);
    }
    if (o < CI){
        #pragma unroll
        for (int i=0;i<16;i++) g_xin[((size_t)b*L_+l0+i)*CI + o] = acc[i];
    } else {
        int c = o - CI;
        #pragma unroll
        for (int i=0;i<16;i++) g_z[((size_t)b*L_+l0+i)*CI + c] = siluf(acc[i]);
    }
}

// ---------------- K2: depthwise 3x3x3 conv + silu, ysum partial init ----------------
__global__ void k2_conv(const float* __restrict__ convb){
    int b = blockIdx.x >> 11;
    int l = blockIdx.x & 2047;
    int h = l>>7, w=(l>>3)&15, d=l&7;
    int c = threadIdx.x;
    float acc = convb[c];
    const float* base = g_xin + (size_t)b*L_*CI;
    #pragma unroll
    for (int kh=0;kh<3;kh++){
        int hh=h+kh-1; if(hh<0||hh>15) continue;
        #pragma unroll
        for (int kw=0;kw<3;kw++){
            int ww=w+kw-1; if(ww<0||ww>15) continue;
            #pragma unroll
            for (int kd=0;kd<3;kd++){
                int dd=d+kd-1; if(dd<0||dd>7) continue;
                int lp=(hh*16+ww)*8+dd;
                acc = fmaf(base[(size_t)lp*CI+c], g_convWT[(kh*9+kw*3+kd)*CI+c], acc);
            }
        }
    }
    float v = siluf(acc);
    size_t idx = ((size_t)b*L_+l)*CI+c;
    g_xc[idx]   = v;
    g_ysum[idx] = g_Dsum[c]*v;
}

// ---------------- K2b: misaligned D*u terms for dirs 3/9 and 4/10 ----------------
__global__ void k2b_dfix(){
    int b = blockIdx.x >> 11;
    int F = blockIdx.x & 2047;
    int c = threadIdx.x;
    // dir3 spec: F = d*256 + h*16 + w  -> source S = (h*16+w)*8+d
    int d3 = F>>8, h3 = (F>>4)&15, w3 = F&15;
    int S3 = (h3*16+w3)*8 + d3;
    // dir4 spec: F = w*128 + d*16 + h  -> source S = (h*16+w)*8+d
    int w4 = F>>7, d4 = (F>>4)&7, h4 = F&15;
    int S4 = (h4*16+w4)*8 + d4;
    const float* xcb = g_xc + (size_t)b*L_*CI + c;
    g_ysum[((size_t)b*L_+F)*CI + c] += g_D3[c]*xcb[(size_t)S3*CI] + g_D4[c]*xcb[(size_t)S4*CI];
}

// ---------------- K3: per-direction projection + dt expansion ----------------
#define K3_T 8
__global__ void k3_proj(const float* __restrict__ xpw,
                        const float* __restrict__ dtw,
                        const float* __restrict__ dtb){
    int tb = blockIdx.x & 255;
    int k  = (blockIdx.x >> 8) % KG;
    int b  = blockIdx.x / (KG*256);
    int t0 = tb*K3_T;
    __shared__ float xs[K3_T][CI];
    __shared__ float xdbl[K3_T][40];
    const float* xcb = g_xc + (size_t)b*L_*CI;
    for (int i=threadIdx.x; i<K3_T*(CI/4); i+=blockDim.x){
        int t=i/(CI/4), q=i%(CI/4);
        int pos = g_src[k*L_ + t0 + t];
        ((float4*)&xs[t][0])[q] = ((const float4*)(xcb + (size_t)pos*CI))[q];
    }
    __syncthreads();
    {   // 8 t x 40 o
        int t = threadIdx.x / 40;
        int o = threadIdx.x % 40;
        float acc = 0.f;
        if (o < 38){
            const float4* wrow = (const float4*)(xpw + ((size_t)k*38 + o)*CI);
            const float4* xr   = (const float4*)&xs[t][0];
            #pragma unroll 4
            for (int q=0;q<CI/4;q++){
                float4 wv = wrow[q]; float4 xv = xr[q];
                acc = fmaf(wv.x,xv.x,acc); acc = fmaf(wv.y,xv.y,acc);
                acc = fmaf(wv.z,xv.z,acc); acc = fmaf(wv.w,xv.w,acc);
            }
        }
        xdbl[t][o] = acc;
    }
    __syncthreads();
    size_t baseO = (size_t)(b*KG+k)*L_ + t0;
    for (int i=threadIdx.x; i<K3_T*CI; i+=blockDim.x){
        int t=i/CI, c=i%CI;
        float raw = dtb[k*CI+c];
        const float* dw = dtw + ((size_t)k*CI + c)*6;
        #pragma unroll
        for (int r=0;r<6;r++) raw = fmaf(dw[r], xdbl[t][r], raw);
        float dt = softplusf(raw);
        float u  = xs[t][c];
        g_dtdu[(baseO + t)*CI + c] = make_float2(dt, dt*u);
    }
    for (int i=threadIdx.x; i<K3_T*8; i+=blockDim.x){
        int t=i/8, j=i%8;
        g_BC[(baseO+t)*8 + j] = make_float4(xdbl[t][6+2*j],  xdbl[t][22+2*j],
                                            xdbl[t][7+2*j],  xdbl[t][23+2*j]);
    }
}

// ---------------- K4: spatial selective scan (12 directions) ----------------
__global__ void __launch_bounds__(256) k4_scan(const float* __restrict__ Alogs){
    int cg = blockIdx.x % 6;
    int k  = (blockIdx.x/6) % KG;
    int b  = blockIdx.x/(6*KG);
    __shared__ int pos_s[L_];
    for (int i=threadIdx.x;i<L_;i+=256) pos_s[i]=g_dst[k*L_+i];
    int warp = threadIdx.x>>5;
    int lane = threadIdx.x&31;
    int il = lane>>3, j = lane&7;
    int c = cg*32 + warp*4 + il;
    float a0 = -__expf(Alogs[(size_t)(k*CI+c)*NS + 2*j]);
    float a1 = -__expf(Alogs[(size_t)(k*CI+c)*NS + 2*j+1]);
    __syncthreads();
    const float2* dp = g_dtdu + (size_t)(b*KG+k)*L_*CI + c;
    const float4* bp = g_BC   + (size_t)(b*KG+k)*L_*8  + j;
    float* ys = g_ysum + (size_t)b*L_*CI + c;
    float h0=0.f, h1=0.f;
    #pragma unroll 4
    for (int t=0;t<L_;t++){
        float2 f = dp[(size_t)t*CI];
        float4 g = bp[(size_t)t*8];
        float dA0 = __expf(f.x*a0);
        float dA1 = __expf(f.x*a1);
        h0 = h0*dA0 + f.y*g.x;
        h1 = h1*dA1 + f.y*g.z;
        float y = h0*g.y + h1*g.w;
        y += __shfl_xor_sync(0xffffffffu, y, 1);
        y += __shfl_xor_sync(0xffffffffu, y, 2);
        y += __shfl_xor_sync(0xffffffffu, y, 4);
        if (j==0) atomicAdd(ys + (size_t)pos_s[t]*CI, y);
    }
}

// ---------------- K5: channel down-proj ----------------
__global__ void k5_down(const float* __restrict__ dww){
    int lch = blockIdx.x & 7;
    int pt  = (blockIdx.x>>3) & 15;
    int b   = blockIdx.x>>7;
    int p0 = pt*8, l0 = lch*256;
    __shared__ float ws[8][256];
    for (int i=threadIdx.x;i<8*256;i+=192){
        int pi=i>>8, li=i&255;
        ws[pi][li] = dww[(size_t)(p0+pi)*L_ + l0+li];
    }
    __syncthreads();
    int c = threadIdx.x;
    float acc[8] = {0,0,0,0,0,0,0,0};
    const float* xb = g_xc + ((size_t)b*L_ + l0)*CI + c;
    for (int li=0;li<256;li++){
        float xv = xb[(size_t)li*CI];
        #pragma unroll
        for (int pi=0;pi<8;pi++) acc[pi] = fmaf(xv, ws[pi][li], acc[pi]);
    }
    #pragma unroll
    for (int pi=0;pi<8;pi++)
        atomicAdd(&g_xd[((size_t)b*DP + p0+pi)*CI + c], acc[pi]);
}

// ---------------- K6: channel projection + softplus ----------------
__global__ void k6_chproj(const float* __restrict__ xpcw,
                          const float* __restrict__ dtcw,
                          const float* __restrict__ dtcb){
    int t = blockIdx.x % CI;
    int b = blockIdx.x / CI;
    __shared__ float col[DP];
    __shared__ float sdbl[40];
    int p = threadIdx.x;
    col[p] = g_xd[((size_t)b*DP + p)*CI + t];
    __syncthreads();
    if (p < 40){
        float acc=0.f;
        for (int q=0;q<DP;q++) acc = fmaf(xpcw[(size_t)p*DP+q], col[q], acc);
        sdbl[p]=acc;
    }
    __syncthreads();
    {
        float raw = dtcb[p];
        #pragma unroll
        for (int r=0;r<8;r++) raw = fmaf(dtcw[p*8+r], sdbl[r], raw);
        g_dtc[((size_t)b*DP+p)*CI + t] = softplusf(raw);
    }
    if (p < 8){
        g_BCc[((size_t)b*CI + t)*8 + p] = make_float4(sdbl[8+2*p],  sdbl[24+2*p],
                                                      sdbl[9+2*p],  sdbl[25+2*p]);
    }
}

// ---------------- K7: channel selective scan ----------------
__global__ void k7_chscan(const float* __restrict__ Alc, const float* __restrict__ Dsc){
    int cb = blockIdx.x % 8;
    int b  = blockIdx.x / 8;
    int warp = threadIdx.x>>5, lane=threadIdx.x&31;
    int il = lane>>3, j=lane&7;
    int ch = cb*16 + warp*4 + il;
    float a0 = -__expf(Alc[ch*NS + 2*j]);
    float a1 = -__expf(Alc[ch*NS + 2*j+1]);
    float Dv = Dsc[ch];
    const float* dtp  = g_dtc + ((size_t)b*DP+ch)*CI;
    const float* up   = g_xd  + ((size_t)b*DP+ch)*CI;
    const float4* bp  = g_BCc + (size_t)b*CI*8 + j;
    float* yp = g_yc + ((size_t)b*DP+ch)*CI;
    float h0=0.f, h1=0.f;
    for (int t=0;t<CI;t++){
        float dt = dtp[t], u = up[t];
        float4 g = bp[(size_t)t*8];
        float du = dt*u;
        h0 = h0*__expf(dt*a0) + du*g.x;
        h1 = h1*__expf(dt*a1) + du*g.z;
        float y = h0*g.y + h1*g.w;
        y += __shfl_xor_sync(0xffffffffu,y,1);
        y += __shfl_xor_sync(0xffffffffu,y,2);
        y += __shfl_xor_sync(0xffffffffu,y,4);
        if (j==0) yp[t] = y + Dv*u;
    }
}

// ---------------- K8: channel up-proj, add into ysum ----------------
__global__ void k8_up(const float* __restrict__ upw, const float* __restrict__ upb){
    int lt = blockIdx.x & 127;
    int b  = blockIdx.x >> 7;
    int l0 = lt*16;
    __shared__ float ws[16][DP];
    for (int i=threadIdx.x;i<16*DP;i+=192)
        ((float*)ws)[i] = upw[(size_t)l0*DP + i];
    __syncthreads();
    int c = threadIdx.x;
    float acc[16];
    #pragma unroll
    for (int i=0;i<16;i++) acc[i]=0.f;
    const float* yb = g_yc + (size_t)b*DP*CI + c;
    for (int ch=0;ch<DP;ch++){
        float yv = yb[(size_t)ch*CI];
        #pragma unroll
        for (int i=0;i<16;i++) acc[i] = fmaf(yv, ws[i][ch], acc[i]);
    }
    #pragma unroll
    for (int i=0;i<16;i++){
        size_t idx = ((size_t)b*L_ + l0+i)*CI + c;
        g_ysum[idx] += acc[i] + upb[l0+i];
    }
}

// ---------------- K9: LayerNorm + gate + out_proj ----------------
__global__ void k9_final(const float* __restrict__ nw, const float* __restrict__ nb,
                         float* __restrict__ out){
    int l = blockIdx.x & 2047;
    int b = blockIdx.x >> 11;
    int c = threadIdx.x;
    __shared__ float gbuf[CI];
    __shared__ float obuf[CI];
    __shared__ float red[6];
    size_t base = ((size_t)b*L_ + l)*CI;
    float y = g_ysum[base + c];
    float s = y;
    #pragma unroll
    for (int o=16;o>0;o>>=1) s += __shfl_xor_sync(0xffffffffu,s,o);
    int warp=c>>5, lane=c&31;
    if (lane==0) red[warp]=s;
    __syncthreads();
    float mu = (red[0]+red[1]+red[2]+red[3]+red[4]+red[5]) * (1.f/CI);
    float d = y - mu;
    float s2 = d*d;
    #pragma unroll
    for (int o=16;o>0;o>>=1) s2 += __shfl_xor_sync(0xffffffffu,s2,o);
    __syncthreads();
    if (lane==0) red[warp]=s2;
    __syncthreads();
    float var = (red[0]+red[1]+red[2]+red[3]+red[4]+red[5]) * (1.f/CI);
    float rstd = rsqrtf(var + 1e-5f);
    float yn = d*rstd*nw[c] + nb[c];
    gbuf[c] = yn * g_z[base + c];
    __syncthreads();
    int m = c % CM, half = c / CM;
    float acc=0.f;
    #pragma unroll 4
    for (int q=0;q<CM;q++){
        int cc = half*CM + q;
        acc = fmaf(gbuf[cc], g_WoutT[cc*CM + m], acc);
    }
    obuf[c]=acc;
    __syncthreads();
    if (half==0)
        out[((size_t)b*L_ + l)*CM + m] = acc + obuf[m+CM];
}

// ---------------- launch ----------------
extern "C" void kernel_launch(void* const* d_in, const int* in_sizes, int n_in,
                              void* d_out, int out_size){
    (void)in_sizes; (void)n_in; (void)out_size;
    const float* x    = (const float*)d_in[0];
    const float* inw  = (const float*)d_in[1];
    const float* convw= (const float*)d_in[2];
    const float* convb= (const float*)d_in[3];
    const float* xpw  = (const float*)d_in[4];
    const float* dtw  = (const float*)d_in[5];
    const float* dtb  = (const float*)d_in[6];
    const float* Alogs= (const float*)d_in[7];
    const float* Ds   = (const float*)d_in[8];
    const float* xpcw = (const float*)d_in[9];
    const float* dtcw = (const float*)d_in[10];
    const float* dtcb = (const float*)d_in[11];
    const float* Alc  = (const float*)d_in[12];
    const float* Dsc  = (const float*)d_in[13];
    const float* dww  = (const float*)d_in[14];
    const float* dwb  = (const float*)d_in[15];
    const float* upw  = (const float*)d_in[16];
    const float* upb  = (const float*)d_in[17];
    const float* nw   = (const float*)d_in[18];
    const float* nb   = (const float*)d_in[19];
    const float* outw = (const float*)d_in[20];
    float* out = (float*)d_out;

    k_prep    <<<128, 256>>>(inw, convw, Ds, dwb, outw);
    k1_inproj <<<B_*128, 384>>>(x);
    k2_conv   <<<B_*L_, CI>>>(convb);
    k2b_dfix  <<<B_*L_, CI>>>();
    k3_proj   <<<B_*KG*256, 320>>>(xpw, dtw, dtb);
    k4_scan   <<<B_*KG*6, 256>>>(Alogs);
    k5_down   <<<256, 192>>>(dww);
    k6_chproj <<<B_*CI, 128>>>(xpcw, dtcw, dtcb);
    k7_chscan <<<B_*8, 128>>>(Alc, Dsc);
    k8_up     <<<B_*128, 192>>>(upw, upb);
    k9_final  <<<B_*L_, CI>>>(nw, nb, out);
}

// round 6
// speedup vs baseline: 2.7071x; 2.7071x over previous
#include <cuda_runtime.h>
#include <cuda_bf16.h>
#include <math.h>

#define B_ 2
#define L_ 2048
#define CM 96
#define CI 192
#define NS 16
#define KG 12
#define DP 128

// ---------------- scratch (device globals, no allocation) ----------------
__device__ float  g_xin[B_*L_*CI];      // [b][l][c] pre-conv
__device__ float  g_z[B_*L_*CI];        // [b][l][c] silu(z)
__device__ float  g_xc[B_*L_*CI];       // [b][l][c] post conv+silu
__device__ float  g_ysum[B_*L_*CI];     // [b][F][c] accumulated y
__device__ float  g_WinT[CM*2*CI];      // [j][o]
__device__ float  g_WoutT[CI*CM];       // [c][m]
__device__ float  g_convWT[27*CI];      // [tap][c]
__device__ int    g_src[KG*L_];         // scan index -> gather spatial pos
__device__ int    g_dst[KG*L_];         // scan index -> scatter flat pos
__device__ float  g_Dsum[CI];
__device__ float  g_D3[CI];
__device__ float  g_D4[CI];
__device__ float2 g_dtdu[B_*KG*L_*CI];  // [b][k][t][c] {dt, dt*u}
__device__ float4 g_BC[B_*KG*L_*8];     // [b][k][t][j] {B2j,C2j,B2j+1,C2j+1}
__device__ float  g_xd[B_*DP*CI];       // [b][p][t]
__device__ float  g_dtc[B_*DP*CI];      // [b][ch][t]
__device__ float4 g_BCc[B_*CI*8];       // [b][t][j]
__device__ float  g_yc[B_*DP*CI];       // [b][ch][t]

__device__ __forceinline__ float softplusf(float x){
    return (x > 20.f) ? x : log1pf(expf(x));
}
__device__ __forceinline__ float siluf(float x){
    return x / (1.f + __expf(-x));
}

// ---------------- prep: tables, transposes, inits ----------------
__global__ void k_prep(const float* __restrict__ inw, const float* __restrict__ convw,
                       const float* __restrict__ Ds, const float* __restrict__ downb,
                       const float* __restrict__ outw){
    int i0 = blockIdx.x*blockDim.x + threadIdx.x;
    int T  = gridDim.x*blockDim.x;
    for (int i=i0; i<CM*2*CI; i+=T){ int j=i/(2*CI), o=i%(2*CI); g_WinT[i]=inw[o*CM+j]; }
    for (int i=i0; i<CI*CM;   i+=T){ int c=i/CM,     m=i%CM;     g_WoutT[i]=outw[m*CI+c]; }
    for (int i=i0; i<27*CI;   i+=T){ int tap=i/CI,   c=i%CI;     g_convWT[i]=convw[c*27+tap]; }
    for (int i=i0; i<KG*L_;   i+=T){
        int k=i/L_, t=i%L_;
        int tt = (k>=6) ? (L_-1-t) : t;
        int h,w,d,F;
        switch(k%6){
            case 0: h=tt>>7; w=(tt>>3)&15; d=tt&7;  F=(h*16+w)*8+d;  break;
            case 1: h=tt>>7; d=(tt>>4)&7;  w=tt&15; F=(h*16+w)*8+d;  break;
            case 2: w=tt>>7; h=(tt>>3)&15; d=tt&7;  F=(h*16+w)*8+d;  break;
            case 3: w=tt>>7; d=(tt>>4)&7;  h=tt&15; F=d*256+h*16+w;  break;
            case 4: d=tt>>8; h=(tt>>4)&15; w=tt&15; F=w*128+d*16+h;  break;
            default:d=tt>>8; w=(tt>>4)&15; h=tt&15; F=(h*16+w)*8+d;  break;
        }
        g_src[i] = (h*16+w)*8+d;
        g_dst[i] = F;
    }
    for (int i=i0; i<CI; i+=T){
        float sa=0.f, s3=0.f, s4=0.f;
        #pragma unroll
        for (int k=0;k<KG;k++){
            float v = Ds[k*CI+i];
            int km = k%6;
            if (km==3) s3 += v;
            else if (km==4) s4 += v;
            else sa += v;
        }
        g_Dsum[i]=sa; g_D3[i]=s3; g_D4[i]=s4;
    }
    for (int i=i0; i<B_*DP*CI; i+=T){
        int p=(i/CI)%DP;
        g_xd[i]=downb[p];
    }
}

// ---------------- K1: in_proj GEMM, split xin / silu(z) ----------------
__global__ void k1_inproj(const float* __restrict__ x){
    int b  = blockIdx.x >> 7;
    int l0 = (blockIdx.x & 127) << 4;
    __shared__ __align__(16) float xs[16][CM];
    const float* src = x + ((size_t)b*L_ + l0)*CM;
    for (int i=threadIdx.x; i<16*CM; i+=384) ((float*)xs)[i] = src[i];
    __syncthreads();
    int o = threadIdx.x;
    float acc[16];
    #pragma unroll
    for (int i=0;i<16;i++) acc[i]=0.f;
    for (int j=0;j<CM;j+=4){
        float w0 = g_WinT[(j  )*(2*CI)+o];
        float w1 = g_WinT[(j+1)*(2*CI)+o];
        float w2 = g_WinT[(j+2)*(2*CI)+o];
        float w3 = g_WinT[(j+3)*(2*CI)+o];
        #pragma unroll
        for (int i=0;i<16;i++){
            float4 xv = *(const float4*)&xs[i][j];
            acc[i] = fmaf(w0,xv.x, fmaf(w1,xv.y, fmaf(w2,xv.z, fmaf(w3,xv.w, acc[i]))));
        }
    }
    if (o < CI){
        #pragma unroll
        for (int i=0;i<16;i++) g_xin[((size_t)b*L_+l0+i)*CI + o] = acc[i];
    } else {
        int c = o - CI;
        #pragma unroll
        for (int i=0;i<16;i++) g_z[((size_t)b*L_+l0+i)*CI + c] = siluf(acc[i]);
    }
}

// ---------------- K2: depthwise 3x3x3 conv + silu, ysum partial init ----------------
__global__ void k2_conv(const float* __restrict__ convb){
    int b = blockIdx.x >> 11;
    int l = blockIdx.x & 2047;
    int h = l>>7, w=(l>>3)&15, d=l&7;
    int c = threadIdx.x;
    float acc = convb[c];
    const float* base = g_xin + (size_t)b*L_*CI;
    #pragma unroll
    for (int kh=0;kh<3;kh++){
        int hh=h+kh-1; if(hh<0||hh>15) continue;
        #pragma unroll
        for (int kw=0;kw<3;kw++){
            int ww=w+kw-1; if(ww<0||ww>15) continue;
            #pragma unroll
            for (int kd=0;kd<3;kd++){
                int dd=d+kd-1; if(dd<0||dd>7) continue;
                int lp=(hh*16+ww)*8+dd;
                acc = fmaf(base[(size_t)lp*CI+c], g_convWT[(kh*9+kw*3+kd)*CI+c], acc);
            }
        }
    }
    float v = siluf(acc);
    size_t idx = ((size_t)b*L_+l)*CI+c;
    g_xc[idx]   = v;
    g_ysum[idx] = g_Dsum[c]*v;
}

// ---------------- K2b: misaligned D*u terms for dirs 3/9 and 4/10 ----------------
__global__ void k2b_dfix(){
    int b = blockIdx.x >> 11;
    int F = blockIdx.x & 2047;
    int c = threadIdx.x;
    int d3 = F>>8, h3 = (F>>4)&15, w3 = F&15;
    int S3 = (h3*16+w3)*8 + d3;
    int w4 = F>>7, d4 = (F>>4)&7, h4 = F&15;
    int S4 = (h4*16+w4)*8 + d4;
    const float* xcb = g_xc + (size_t)b*L_*CI + c;
    g_ysum[((size_t)b*L_+F)*CI + c] += g_D3[c]*xcb[(size_t)S3*CI] + g_D4[c]*xcb[(size_t)S4*CI];
}

// ---------------- K3: per-direction projection + dt expansion (smem-staged weights) ----------------
// grid: B_*KG*16 blocks, each handles 128 t of one (b,k); 16 subiters of 8 t.
__global__ void __launch_bounds__(256) k3_proj(const float* __restrict__ xpw,
                        const float* __restrict__ dtw,
                        const float* __restrict__ dtb){
    int tcb = blockIdx.x & 15;
    int k   = (blockIdx.x >> 4) % KG;
    int b   = blockIdx.x / (16*KG);
    int T0  = tcb*128;
    __shared__ __align__(16) float ws  [38*CI];   // xpw slice [o][d]
    __shared__ __align__(16) float wdt [CI*6];    // dt_projs_weight slice [c][r]
    __shared__             float wdtb[CI];
    __shared__ __align__(16) float xs  [8][CI];
    __shared__             float xdbl[8][40];
    int tid = threadIdx.x;
    // stage weights once
    for (int i=tid; i<38*CI; i+=256) ws[i]  = xpw[(size_t)k*38*CI + i];
    for (int i=tid; i<CI*6;  i+=256) wdt[i] = dtw[(size_t)k*CI*6  + i];
    for (int i=tid; i<CI;    i+=256) wdtb[i]= dtb[k*CI + i];
    const float* xcb = g_xc + (size_t)b*L_*CI;
    const float4* ws4 = (const float4*)ws;
    size_t baseBK = (size_t)(b*KG+k)*L_;
    for (int sub=0; sub<16; sub++){
        int t0g = T0 + sub*8;
        __syncthreads();   // xs free (first iter: after weight stage)
        // load 8 gathered rows
        for (int i=tid; i<8*(CI/4); i+=256){
            int t=i/(CI/4), q=i%(CI/4);
            int pos = g_src[k*L_ + t0g + t];
            ((float4*)&xs[t][0])[q] = ((const float4*)(xcb + (size_t)pos*CI))[q];
        }
        __syncthreads();
        // GEMM: 2t x 2o register tiles; 76 threads
        if (tid < 76){
            int tp = tid/19, op = tid%19;
            int t0=2*tp, t1=2*tp+1, o0=2*op, o1=2*op+1;
            const float4* x0 = (const float4*)&xs[t0][0];
            const float4* x1 = (const float4*)&xs[t1][0];
            float a00=0.f,a01=0.f,a10=0.f,a11=0.f;
            #pragma unroll 4
            for (int q=0;q<CI/4;q++){
                float4 xv0=x0[q], xv1=x1[q];
                float4 w0=ws4[o0*(CI/4)+q], w1=ws4[o1*(CI/4)+q];
                a00=fmaf(w0.x,xv0.x,fmaf(w0.y,xv0.y,fmaf(w0.z,xv0.z,fmaf(w0.w,xv0.w,a00))));
                a01=fmaf(w1.x,xv0.x,fmaf(w1.y,xv0.y,fmaf(w1.z,xv0.z,fmaf(w1.w,xv0.w,a01))));
                a10=fmaf(w0.x,xv1.x,fmaf(w0.y,xv1.y,fmaf(w0.z,xv1.z,fmaf(w0.w,xv1.w,a10))));
                a11=fmaf(w1.x,xv1.x,fmaf(w1.y,xv1.y,fmaf(w1.z,xv1.z,fmaf(w1.w,xv1.w,a11))));
            }
            xdbl[t0][o0]=a00; xdbl[t0][o1]=a01;
            xdbl[t1][o0]=a10; xdbl[t1][o1]=a11;
        }
        __syncthreads();
        // dt expansion + dtdu store (coalesced, [t][c])
        #pragma unroll
        for (int p=0;p<6;p++){
            int i = tid + p*256;
            int t = i/CI, c = i%CI;
            float raw = wdtb[c];
            #pragma unroll
            for (int r=0;r<6;r++) raw = fmaf(wdt[c*6+r], xdbl[t][r], raw);
            float dt = softplusf(raw);
            float u  = xs[t][c];
            g_dtdu[(baseBK + t0g + t)*CI + c] = make_float2(dt, dt*u);
        }
        if (tid < 64){
            int t=tid/8, j=tid%8;
            g_BC[(baseBK + t0g + t)*8 + j] = make_float4(xdbl[t][6+2*j],  xdbl[t][22+2*j],
                                                         xdbl[t][7+2*j],  xdbl[t][23+2*j]);
        }
    }
}

// ---------------- K4: spatial selective scan, prefetch + phase-split ----------------
#define U4 8
__global__ void __launch_bounds__(256) k4_scan(const float* __restrict__ Alogs){
    int cg = blockIdx.x % 6;
    int k  = (blockIdx.x/6) % KG;
    int b  = blockIdx.x/(6*KG);
    __shared__ int pos_s[L_];
    for (int i=threadIdx.x;i<L_;i+=256) pos_s[i]=g_dst[k*L_+i];
    int warp = threadIdx.x>>5;
    int lane = threadIdx.x&31;
    int il = lane>>3, j = lane&7;
    int c = cg*32 + warp*4 + il;
    float a0 = -__expf(Alogs[(size_t)(k*CI+c)*NS + 2*j]);
    float a1 = -__expf(Alogs[(size_t)(k*CI+c)*NS + 2*j+1]);
    __syncthreads();
    const float2* dp = g_dtdu + (size_t)(b*KG+k)*L_*CI + c;
    const float4* bp = g_BC   + (size_t)(b*KG+k)*L_*8  + j;
    float* ys = g_ysum + (size_t)b*L_*CI + c;
    float h0=0.f, h1=0.f;
    float2 fb[U4]; float4 gb[U4];
    #pragma unroll
    for (int i=0;i<U4;i++){ fb[i]=dp[(size_t)i*CI]; gb[i]=bp[(size_t)i*8]; }
    for (int t0=0; t0<L_; t0+=U4){
        float yv[U4];
        int tn = t0 + U4;
        #pragma unroll
        for (int i=0;i<U4;i++){
            float2 fc = fb[i]; float4 gc = gb[i];
            if (tn < L_){
                fb[i]=dp[(size_t)(tn+i)*CI];
                gb[i]=bp[(size_t)(tn+i)*8];
            }
            float dA0 = __expf(fc.x*a0);
            float dA1 = __expf(fc.x*a1);
            h0 = h0*dA0 + fc.y*gc.x;
            h1 = h1*dA1 + fc.y*gc.z;
            yv[i] = h0*gc.y + h1*gc.w;
        }
        #pragma unroll
        for (int i=0;i<U4;i++) yv[i] += __shfl_xor_sync(0xffffffffu, yv[i], 1);
        #pragma unroll
        for (int i=0;i<U4;i++) yv[i] += __shfl_xor_sync(0xffffffffu, yv[i], 2);
        #pragma unroll
        for (int i=0;i<U4;i++) yv[i] += __shfl_xor_sync(0xffffffffu, yv[i], 4);
        if (j==0){
            #pragma unroll
            for (int i=0;i<U4;i++)
                atomicAdd(ys + (size_t)pos_s[t0+i]*CI, yv[i]);
        }
    }
}

// ---------------- K5: channel down-proj ----------------
__global__ void k5_down(const float* __restrict__ dww){
    int lch = blockIdx.x & 7;
    int pt  = (blockIdx.x>>3) & 15;
    int b   = blockIdx.x>>7;
    int p0 = pt*8, l0 = lch*256;
    __shared__ float ws[8][256];
    for (int i=threadIdx.x;i<8*256;i+=192){
        int pi=i>>8, li=i&255;
        ws[pi][li] = dww[(size_t)(p0+pi)*L_ + l0+li];
    }
    __syncthreads();
    int c = threadIdx.x;
    float acc[8] = {0,0,0,0,0,0,0,0};
    const float* xb = g_xc + ((size_t)b*L_ + l0)*CI + c;
    for (int li=0;li<256;li++){
        float xv = xb[(size_t)li*CI];
        #pragma unroll
        for (int pi=0;pi<8;pi++) acc[pi] = fmaf(xv, ws[pi][li], acc[pi]);
    }
    #pragma unroll
    for (int pi=0;pi<8;pi++)
        atomicAdd(&g_xd[((size_t)b*DP + p0+pi)*CI + c], acc[pi]);
}

// ---------------- K6: channel projection + softplus ----------------
__global__ void k6_chproj(const float* __restrict__ xpcw,
                          const float* __restrict__ dtcw,
                          const float* __restrict__ dtcb){
    int t = blockIdx.x % CI;
    int b = blockIdx.x / CI;
    __shared__ float col[DP];
    __shared__ float sdbl[40];
    int p = threadIdx.x;
    col[p] = g_xd[((size_t)b*DP + p)*CI + t];
    __syncthreads();
    if (p < 40){
        float acc=0.f;
        for (int q=0;q<DP;q++) acc = fmaf(xpcw[(size_t)p*DP+q], col[q], acc);
        sdbl[p]=acc;
    }
    __syncthreads();
    {
        float raw = dtcb[p];
        #pragma unroll
        for (int r=0;r<8;r++) raw = fmaf(dtcw[p*8+r], sdbl[r], raw);
        g_dtc[((size_t)b*DP+p)*CI + t] = softplusf(raw);
    }
    if (p < 8){
        g_BCc[((size_t)b*CI + t)*8 + p] = make_float4(sdbl[8+2*p],  sdbl[24+2*p],
                                                      sdbl[9+2*p],  sdbl[25+2*p]);
    }
}

// ---------------- K7: channel selective scan, prefetch + phase-split ----------------
#define U7 8
__global__ void k7_chscan(const float* __restrict__ Alc, const float* __restrict__ Dsc){
    int cb = blockIdx.x % 8;
    int b  = blockIdx.x / 8;
    int warp = threadIdx.x>>5, lane=threadIdx.x&31;
    int il = lane>>3, j=lane&7;
    int ch = cb*16 + warp*4 + il;
    float a0 = -__expf(Alc[ch*NS + 2*j]);
    float a1 = -__expf(Alc[ch*NS + 2*j+1]);
    float Dv = Dsc[ch];
    const float* dtp  = g_dtc + ((size_t)b*DP+ch)*CI;
    const float* up   = g_xd  + ((size_t)b*DP+ch)*CI;
    const float4* bp  = g_BCc + (size_t)b*CI*8 + j;
    float* yp = g_yc + ((size_t)b*DP+ch)*CI;
    float h0=0.f, h1=0.f;
    float db[U7], ub[U7]; float4 gb[U7];
    #pragma unroll
    for (int i=0;i<U7;i++){ db[i]=dtp[i]; ub[i]=up[i]; gb[i]=bp[(size_t)i*8]; }
    for (int t0=0; t0<CI; t0+=U7){
        float yv[U7], uc[U7];
        int tn = t0 + U7;
        #pragma unroll
        for (int i=0;i<U7;i++){
            float dt=db[i], u=ub[i]; float4 g=gb[i];
            uc[i]=u;
            if (tn < CI){ db[i]=dtp[tn+i]; ub[i]=up[tn+i]; gb[i]=bp[(size_t)(tn+i)*8]; }
            float du = dt*u;
            h0 = h0*__expf(dt*a0) + du*g.x;
            h1 = h1*__expf(dt*a1) + du*g.z;
            yv[i] = h0*g.y + h1*g.w;
        }
        #pragma unroll
        for (int i=0;i<U7;i++) yv[i] += __shfl_xor_sync(0xffffffffu,yv[i],1);
        #pragma unroll
        for (int i=0;i<U7;i++) yv[i] += __shfl_xor_sync(0xffffffffu,yv[i],2);
        #pragma unroll
        for (int i=0;i<U7;i++) yv[i] += __shfl_xor_sync(0xffffffffu,yv[i],4);
        if (j==0){
            #pragma unroll
            for (int i=0;i<U7;i++) yp[t0+i] = yv[i] + Dv*uc[i];
        }
    }
}

// ---------------- K8: channel up-proj, add into ysum ----------------
__global__ void k8_up(const float* __restrict__ upw, const float* __restrict__ upb){
    int lt = blockIdx.x & 127;
    int b  = blockIdx.x >> 7;
    int l0 = lt*16;
    __shared__ float ws[16][DP];
    for (int i=threadIdx.x;i<16*DP;i+=192)
        ((float*)ws)[i] = upw[(size_t)l0*DP + i];
    __syncthreads();
    int c = threadIdx.x;
    float acc[16];
    #pragma unroll
    for (int i=0;i<16;i++) acc[i]=0.f;
    const float* yb = g_yc + (size_t)b*DP*CI + c;
    for (int ch=0;ch<DP;ch++){
        float yv = yb[(size_t)ch*CI];
        #pragma unroll
        for (int i=0;i<16;i++) acc[i] = fmaf(yv, ws[i][ch], acc[i]);
    }
    #pragma unroll
    for (int i=0;i<16;i++){
        size_t idx = ((size_t)b*L_ + l0+i)*CI + c;
        g_ysum[idx] += acc[i] + upb[l0+i];
    }
}

// ---------------- K9: LayerNorm + gate + out_proj ----------------
__global__ void k9_final(const float* __restrict__ nw, const float* __restrict__ nb,
                         float* __restrict__ out){
    int l = blockIdx.x & 2047;
    int b = blockIdx.x >> 11;
    int c = threadIdx.x;
    __shared__ float gbuf[CI];
    __shared__ float obuf[CI];
    __shared__ float red[6];
    size_t base = ((size_t)b*L_ + l)*CI;
    float y = g_ysum[base + c];
    float s = y;
    #pragma unroll
    for (int o=16;o>0;o>>=1) s += __shfl_xor_sync(0xffffffffu,s,o);
    int warp=c>>5, lane=c&31;
    if (lane==0) red[warp]=s;
    __syncthreads();
    float mu = (red[0]+red[1]+red[2]+red[3]+red[4]+red[5]) * (1.f/CI);
    float d = y - mu;
    float s2 = d*d;
    #pragma unroll
    for (int o=16;o>0;o>>=1) s2 += __shfl_xor_sync(0xffffffffu,s2,o);
    __syncthreads();
    if (lane==0) red[warp]=s2;
    __syncthreads();
    float var = (red[0]+red[1]+red[2]+red[3]+red[4]+red[5]) * (1.f/CI);
    float rstd = rsqrtf(var + 1e-5f);
    float yn = d*rstd*nw[c] + nb[c];
    gbuf[c] = yn * g_z[base + c];
    __syncthreads();
    int m = c % CM, half = c / CM;
    float acc=0.f;
    #pragma unroll 4
    for (int q=0;q<CM;q++){
        int cc = half*CM + q;
        acc = fmaf(gbuf[cc], g_WoutT[cc*CM + m], acc);
    }
    obuf[c]=acc;
    __syncthreads();
    if (half==0)
        out[((size_t)b*L_ + l)*CM + m] = acc + obuf[m+CM];
}

// ---------------- launch ----------------
extern "C" void kernel_launch(void* const* d_in, const int* in_sizes, int n_in,
                              void* d_out, int out_size){
    (void)in_sizes; (void)n_in; (void)out_size;
    const float* x    = (const float*)d_in[0];
    const float* inw  = (const float*)d_in[1];
    const float* convw= (const float*)d_in[2];
    const float* convb= (const float*)d_in[3];
    const float* xpw  = (const float*)d_in[4];
    const float* dtw  = (const float*)d_in[5];
    const float* dtb  = (const float*)d_in[6];
    const float* Alogs= (const float*)d_in[7];
    const float* Ds   = (const float*)d_in[8];
    const float* xpcw = (const float*)d_in[9];
    const float* dtcw = (const float*)d_in[10];
    const float* dtcb = (const float*)d_in[11];
    const float* Alc  = (const float*)d_in[12];
    const float* Dsc  = (const float*)d_in[13];
    const float* dww  = (const float*)d_in[14];
    const float* dwb  = (const float*)d_in[15];
    const float* upw  = (const float*)d_in[16];
    const float* upb  = (const float*)d_in[17];
    const float* nw   = (const float*)d_in[18];
    const float* nb   = (const float*)d_in[19];
    const float* outw = (const float*)d_in[20];
    float* out = (float*)d_out;

    k_prep    <<<128, 256>>>(inw, convw, Ds, dwb, outw);
    k1_inproj <<<B_*128, 384>>>(x);
    k2_conv   <<<B_*L_, CI>>>(convb);
    k2b_dfix  <<<B_*L_, CI>>>();
    k3_proj   <<<B_*KG*16, 256>>>(xpw, dtw, dtb);
    k4_scan   <<<B_*KG*6, 256>>>(Alogs);
    k5_down   <<<256, 192>>>(dww);
    k6_chproj <<<B_*CI, 128>>>(xpcw, dtcw, dtcb);
    k7_chscan <<<B_*8, 128>>>(Alc, Dsc);
    k8_up     <<<B_*128, 192>>>(upw, upb);
    k9_final  <<<B_*L_, CI>>>(nw, nb, out);
}

// round 7
// speedup vs baseline: 3.7984x; 1.4031x over previous
#include <cuda_runtime.h>
#include <cuda_bf16.h>
#include <math.h>

#define B_ 2
#define L_ 2048
#define CM 96
#define CI 192
#define NS 16
#define KG 12
#define DP 128

// ---------------- scratch (device globals, no allocation) ----------------
__device__ float  g_xin[B_*L_*CI];      // [b][l][c] pre-conv
__device__ float  g_z[B_*L_*CI];        // [b][l][c] silu(z)
__device__ float  g_xc[B_*L_*CI];       // [b][l][c] post conv+silu
__device__ float  g_ysum[B_*L_*CI];     // [b][F][c] accumulated y
__device__ float  g_ybuf[B_*KG*L_*CI];  // [b][k][F][c] per-direction scan out
__device__ float  g_WinT[CM*2*CI];      // [j][o]
__device__ float  g_WoutT[CI*CM];       // [c][m]
__device__ float  g_convWT[27*CI];      // [tap][c]
__device__ int    g_src[KG*L_];         // scan index -> gather spatial pos
__device__ int    g_dst[KG*L_];         // scan index -> scatter flat pos
__device__ float  g_Dsum[CI];
__device__ float  g_D3[CI];
__device__ float  g_D4[CI];
__device__ float2 g_dtdu[B_*KG*L_*CI];  // [b][k][t][c] {dt, dt*u}
__device__ float4 g_BC[B_*KG*L_*8];     // [b][k][t][j] {B2j,C2j,B2j+1,C2j+1}
__device__ float  g_xd[B_*DP*CI];       // [b][p][t]
__device__ float  g_dtc[B_*DP*CI];      // [b][ch][t]
__device__ float4 g_BCc[B_*CI*8];       // [b][t][j]
__device__ float  g_yc[B_*DP*CI];       // [b][ch][t]

__device__ __forceinline__ float softplusf(float x){
    return (x > 20.f) ? x : log1pf(expf(x));
}
__device__ __forceinline__ float siluf(float x){
    return x / (1.f + __expf(-x));
}

// ---------------- prep: tables, transposes, inits ----------------
__global__ void k_prep(const float* __restrict__ inw, const float* __restrict__ convw,
                       const float* __restrict__ Ds, const float* __restrict__ downb,
                       const float* __restrict__ outw){
    int i0 = blockIdx.x*blockDim.x + threadIdx.x;
    int T  = gridDim.x*blockDim.x;
    for (int i=i0; i<CM*2*CI; i+=T){ int j=i/(2*CI), o=i%(2*CI); g_WinT[i]=inw[o*CM+j]; }
    for (int i=i0; i<CI*CM;   i+=T){ int c=i/CM,     m=i%CM;     g_WoutT[i]=outw[m*CI+c]; }
    for (int i=i0; i<27*CI;   i+=T){ int tap=i/CI,   c=i%CI;     g_convWT[i]=convw[c*27+tap]; }
    for (int i=i0; i<KG*L_;   i+=T){
        int k=i/L_, t=i%L_;
        int tt = (k>=6) ? (L_-1-t) : t;
        int h,w,d,F;
        switch(k%6){
            case 0: h=tt>>7; w=(tt>>3)&15; d=tt&7;  F=(h*16+w)*8+d;  break;
            case 1: h=tt>>7; d=(tt>>4)&7;  w=tt&15; F=(h*16+w)*8+d;  break;
            case 2: w=tt>>7; h=(tt>>3)&15; d=tt&7;  F=(h*16+w)*8+d;  break;
            case 3: w=tt>>7; d=(tt>>4)&7;  h=tt&15; F=d*256+h*16+w;  break;
            case 4: d=tt>>8; h=(tt>>4)&15; w=tt&15; F=w*128+d*16+h;  break;
            default:d=tt>>8; w=(tt>>4)&15; h=tt&15; F=(h*16+w)*8+d;  break;
        }
        g_src[i] = (h*16+w)*8+d;
        g_dst[i] = F;
    }
    for (int i=i0; i<CI; i+=T){
        float sa=0.f, s3=0.f, s4=0.f;
        #pragma unroll
        for (int k=0;k<KG;k++){
            float v = Ds[k*CI+i];
            int km = k%6;
            if (km==3) s3 += v;
            else if (km==4) s4 += v;
            else sa += v;
        }
        g_Dsum[i]=sa; g_D3[i]=s3; g_D4[i]=s4;
    }
    for (int i=i0; i<B_*DP*CI; i+=T){
        int p=(i/CI)%DP;
        g_xd[i]=downb[p];
    }
}

// ---------------- K1: in_proj GEMM, split xin / silu(z) ----------------
__global__ void k1_inproj(const float* __restrict__ x){
    int b  = blockIdx.x >> 7;
    int l0 = (blockIdx.x & 127) << 4;
    __shared__ __align__(16) float xs[16][CM];
    const float* src = x + ((size_t)b*L_ + l0)*CM;
    for (int i=threadIdx.x; i<16*CM; i+=384) ((float*)xs)[i] = src[i];
    __syncthreads();
    int o = threadIdx.x;
    float acc[16];
    #pragma unroll
    for (int i=0;i<16;i++) acc[i]=0.f;
    for (int j=0;j<CM;j+=4){
        float w0 = g_WinT[(j  )*(2*CI)+o];
        float w1 = g_WinT[(j+1)*(2*CI)+o];
        float w2 = g_WinT[(j+2)*(2*CI)+o];
        float w3 = g_WinT[(j+3)*(2*CI)+o];
        #pragma unroll
        for (int i=0;i<16;i++){
            float4 xv = *(const float4*)&xs[i][j];
            acc[i] = fmaf(w0,xv.x, fmaf(w1,xv.y, fmaf(w2,xv.z, fmaf(w3,xv.w, acc[i]))));
        }
    }
    if (o < CI){
        #pragma unroll
        for (int i=0;i<16;i++) g_xin[((size_t)b*L_+l0+i)*CI + o] = acc[i];
    } else {
        int c = o - CI;
        #pragma unroll
        for (int i=0;i<16;i++) g_z[((size_t)b*L_+l0+i)*CI + c] = siluf(acc[i]);
    }
}

// ---------------- K2: depthwise 3x3x3 conv + silu ----------------
__global__ void k2_conv(const float* __restrict__ convb){
    int b = blockIdx.x >> 11;
    int l = blockIdx.x & 2047;
    int h = l>>7, w=(l>>3)&15, d=l&7;
    int c = threadIdx.x;
    float acc = convb[c];
    const float* base = g_xin + (size_t)b*L_*CI;
    #pragma unroll
    for (int kh=0;kh<3;kh++){
        int hh=h+kh-1; if(hh<0||hh>15) continue;
        #pragma unroll
        for (int kw=0;kw<3;kw++){
            int ww=w+kw-1; if(ww<0||ww>15) continue;
            #pragma unroll
            for (int kd=0;kd<3;kd++){
                int dd=d+kd-1; if(dd<0||dd>7) continue;
                int lp=(hh*16+ww)*8+dd;
                acc = fmaf(base[(size_t)lp*CI+c], g_convWT[(kh*9+kw*3+kd)*CI+c], acc);
            }
        }
    }
    g_xc[((size_t)b*L_+l)*CI+c] = siluf(acc);
}

// ---------------- K3: per-direction projection + dt expansion ----------------
// 384 blocks (b,k,128-t chunk); 4 subiters of 32 t; dynamic smem.
#define SUBT 32
#define XR   196   // padded xs row stride (floats)
__global__ void __launch_bounds__(256) k3_proj(const float* __restrict__ xpw,
                        const float* __restrict__ dtw,
                        const float* __restrict__ dtb){
    extern __shared__ __align__(16) float sm3[];
    float* wsT  = sm3;               // [q][o] 192*40
    float* wdt  = wsT + 192*40;      // [c][r] 192*6
    float* wdtb = wdt + 192*6;       // 192
    float* xs   = wdtb + 192;        // SUBT * XR
    float* xdbl = xs + SUBT*XR;      // SUBT * 40
    int tcb = blockIdx.x & 15;
    int k   = (blockIdx.x >> 4) % KG;
    int b   = blockIdx.x / (16*KG);
    int T0  = tcb*128;
    int tid = threadIdx.x;
    // stage weights (transposed for conflict-free GEMM loads)
    for (int i=tid; i<38*CI; i+=256){
        int o=i/CI, q=i%CI;
        wsT[q*40+o] = xpw[(size_t)k*38*CI + i];
    }
    for (int i=tid; i<CI; i+=256){ wsT[i*40+38]=0.f; wsT[i*40+39]=0.f; }
    for (int i=tid; i<CI*6; i+=256) wdt[i]  = dtw[(size_t)k*CI*6 + i];
    for (int i=tid; i<CI;   i+=256) wdtb[i] = dtb[k*CI + i];
    const float* xcb = g_xc + (size_t)b*L_*CI;
    size_t baseBK = (size_t)(b*KG+k)*L_;
    for (int sub=0; sub<4; sub++){
        int t0g = T0 + sub*SUBT;
        __syncthreads();
        // gather 32 rows
        for (int i=tid; i<SUBT*48; i+=256){
            int t=i/48, q=i%48;
            int pos = g_src[k*L_ + t0g + t];
            ((float4*)(xs + t*XR))[q] = ((const float4*)(xcb + (size_t)pos*CI))[q];
        }
        __syncthreads();
        // GEMM: 2t x 4o tiles, 160 active threads
        if (tid < 160){
            int op = tid % 10, tp = tid / 10;
            int t0 = 2*tp, t1 = t0+1;
            const float4* x0 = (const float4*)(xs + t0*XR);
            const float4* x1 = (const float4*)(xs + t1*XR);
            float a00=0,a01=0,a02=0,a03=0, a10=0,a11=0,a12=0,a13=0;
            #pragma unroll 4
            for (int q=0;q<48;q++){
                float4 xv0=x0[q], xv1=x1[q];
                float4 w0 = *(const float4*)(wsT + (4*q  )*40 + 4*op);
                float4 w1 = *(const float4*)(wsT + (4*q+1)*40 + 4*op);
                float4 w2 = *(const float4*)(wsT + (4*q+2)*40 + 4*op);
                float4 w3 = *(const float4*)(wsT + (4*q+3)*40 + 4*op);
                a00=fmaf(xv0.x,w0.x,fmaf(xv0.y,w1.x,fmaf(xv0.z,w2.x,fmaf(xv0.w,w3.x,a00))));
                a01=fmaf(xv0.x,w0.y,fmaf(xv0.y,w1.y,fmaf(xv0.z,w2.y,fmaf(xv0.w,w3.y,a01))));
                a02=fmaf(xv0.x,w0.z,fmaf(xv0.y,w1.z,fmaf(xv0.z,w2.z,fmaf(xv0.w,w3.z,a02))));
                a03=fmaf(xv0.x,w0.w,fmaf(xv0.y,w1.w,fmaf(xv0.z,w2.w,fmaf(xv0.w,w3.w,a03))));
                a10=fmaf(xv1.x,w0.x,fmaf(xv1.y,w1.x,fmaf(xv1.z,w2.x,fmaf(xv1.w,w3.x,a10))));
                a11=fmaf(xv1.x,w0.y,fmaf(xv1.y,w1.y,fmaf(xv1.z,w2.y,fmaf(xv1.w,w3.y,a11))));
                a12=fmaf(xv1.x,w0.z,fmaf(xv1.y,w1.z,fmaf(xv1.z,w2.z,fmaf(xv1.w,w3.z,a12))));
                a13=fmaf(xv1.x,w0.w,fmaf(xv1.y,w1.w,fmaf(xv1.z,w2.w,fmaf(xv1.w,w3.w,a13))));
            }
            float* d0 = xdbl + t0*40 + 4*op;
            float* d1 = xdbl + t1*40 + 4*op;
            d0[0]=a00; d0[1]=a01; d0[2]=a02; d0[3]=a03;
            d1[0]=a10; d1[1]=a11; d1[2]=a12; d1[3]=a13;
        }
        __syncthreads();
        // dt expansion + dtdu store: 24 passes
        #pragma unroll
        for (int p=0;p<24;p++){
            int i = tid + p*256;
            int t = i/CI, c = i%CI;
            float raw = wdtb[c];
            const float* xr = xdbl + t*40;
            #pragma unroll
            for (int r=0;r<6;r++) raw = fmaf(wdt[c*6+r], xr[r], raw);
            float dt = softplusf(raw);
            float u  = xs[t*XR + c];
            g_dtdu[(baseBK + t0g + t)*CI + c] = make_float2(dt, dt*u);
        }
        // BC store: exactly 256 = 32t x 8j
        {
            int t = tid/8, j = tid%8;
            const float* xr = xdbl + t*40;
            g_BC[(baseBK + t0g + t)*8 + j] = make_float4(xr[6+2*j],  xr[22+2*j],
                                                         xr[7+2*j],  xr[23+2*j]);
        }
    }
}

// ---------------- K4: spatial selective scan, deep prefetch, no atomics ----------------
#define U4 16
__global__ void __launch_bounds__(256) k4_scan(const float* __restrict__ Alogs){
    int cg = blockIdx.x % 6;
    int k  = (blockIdx.x/6) % KG;
    int b  = blockIdx.x/(6*KG);
    __shared__ int pos_s[L_];
    for (int i=threadIdx.x;i<L_;i+=256) pos_s[i]=g_dst[k*L_+i];
    int warp = threadIdx.x>>5;
    int lane = threadIdx.x&31;
    int il = lane>>3, j = lane&7;
    int c = cg*32 + warp*4 + il;
    float a0 = -__expf(Alogs[(size_t)(k*CI+c)*NS + 2*j]);
    float a1 = -__expf(Alogs[(size_t)(k*CI+c)*NS + 2*j+1]);
    __syncthreads();
    const float2* dp = g_dtdu + (size_t)(b*KG+k)*L_*CI + c;
    const float4* bp = g_BC   + (size_t)(b*KG+k)*L_*8  + j;
    float* yb = g_ybuf + (size_t)(b*KG+k)*L_*CI + c;
    float h0=0.f, h1=0.f;
    float2 fb[U4]; float4 gb[U4];
    #pragma unroll
    for (int i=0;i<U4;i++){ fb[i]=dp[(size_t)i*CI]; gb[i]=bp[(size_t)i*8]; }
    for (int t0=0; t0<L_; t0+=U4){
        float yv[U4];
        int tn = t0 + U4;
        #pragma unroll
        for (int i=0;i<U4;i++){
            float2 fc = fb[i]; float4 gc = gb[i];
            if (tn < L_){
                fb[i]=dp[(size_t)(tn+i)*CI];
                gb[i]=bp[(size_t)(tn+i)*8];
            }
            float dA0 = __expf(fc.x*a0);
            float dA1 = __expf(fc.x*a1);
            h0 = h0*dA0 + fc.y*gc.x;
            h1 = h1*dA1 + fc.y*gc.z;
            yv[i] = h0*gc.y + h1*gc.w;
        }
        #pragma unroll
        for (int i=0;i<U4;i++) yv[i] += __shfl_xor_sync(0xffffffffu, yv[i], 1);
        #pragma unroll
        for (int i=0;i<U4;i++) yv[i] += __shfl_xor_sync(0xffffffffu, yv[i], 2);
        #pragma unroll
        for (int i=0;i<U4;i++) yv[i] += __shfl_xor_sync(0xffffffffu, yv[i], 4);
        if (j==0){
            #pragma unroll
            for (int i=0;i<U4;i++)
                yb[(size_t)pos_s[t0+i]*CI] = yv[i];
        }
    }
}

// ---------------- K4b: merge 12 direction outputs + all D*u terms ----------------
__global__ void k4b_merge(){
    int b = blockIdx.x >> 11;
    int F = blockIdx.x & 2047;
    int c = threadIdx.x;
    int d3 = F>>8, h3 = (F>>4)&15, w3 = F&15;
    int S3 = (h3*16+w3)*8 + d3;
    int w4 = F>>7, d4 = (F>>4)&7, h4 = F&15;
    int S4 = (h4*16+w4)*8 + d4;
    const float* xcb = g_xc + (size_t)b*L_*CI + c;
    float s = g_Dsum[c]*xcb[(size_t)F*CI]
            + g_D3[c]*xcb[(size_t)S3*CI]
            + g_D4[c]*xcb[(size_t)S4*CI];
    const float* yb = g_ybuf + ((size_t)b*KG*L_ + F)*CI + c;
    #pragma unroll
    for (int k=0;k<KG;k++) s += yb[(size_t)k*L_*CI];
    g_ysum[((size_t)b*L_+F)*CI + c] = s;
}

// ---------------- K5: channel down-proj ----------------
__global__ void k5_down(const float* __restrict__ dww){
    int lch = blockIdx.x & 7;
    int pt  = (blockIdx.x>>3) & 15;
    int b   = blockIdx.x>>7;
    int p0 = pt*8, l0 = lch*256;
    __shared__ float ws[8][256];
    for (int i=threadIdx.x;i<8*256;i+=192){
        int pi=i>>8, li=i&255;
        ws[pi][li] = dww[(size_t)(p0+pi)*L_ + l0+li];
    }
    __syncthreads();
    int c = threadIdx.x;
    float acc[8] = {0,0,0,0,0,0,0,0};
    const float* xb = g_xc + ((size_t)b*L_ + l0)*CI + c;
    for (int li=0;li<256;li++){
        float xv = xb[(size_t)li*CI];
        #pragma unroll
        for (int pi=0;pi<8;pi++) acc[pi] = fmaf(xv, ws[pi][li], acc[pi]);
    }
    #pragma unroll
    for (int pi=0;pi<8;pi++)
        atomicAdd(&g_xd[((size_t)b*DP + p0+pi)*CI + c], acc[pi]);
}

// ---------------- K6: channel projection + softplus ----------------
__global__ void k6_chproj(const float* __restrict__ xpcw,
                          const float* __restrict__ dtcw,
                          const float* __restrict__ dtcb){
    int t = blockIdx.x % CI;
    int b = blockIdx.x / CI;
    __shared__ float col[DP];
    __shared__ float sdbl[40];
    int p = threadIdx.x;
    col[p] = g_xd[((size_t)b*DP + p)*CI + t];
    __syncthreads();
    if (p < 40){
        float acc=0.f;
        for (int q=0;q<DP;q++) acc = fmaf(xpcw[(size_t)p*DP+q], col[q], acc);
        sdbl[p]=acc;
    }
    __syncthreads();
    {
        float raw = dtcb[p];
        #pragma unroll
        for (int r=0;r<8;r++) raw = fmaf(dtcw[p*8+r], sdbl[r], raw);
        g_dtc[((size_t)b*DP+p)*CI + t] = softplusf(raw);
    }
    if (p < 8){
        g_BCc[((size_t)b*CI + t)*8 + p] = make_float4(sdbl[8+2*p],  sdbl[24+2*p],
                                                      sdbl[9+2*p],  sdbl[25+2*p]);
    }
}

// ---------------- K7: channel selective scan ----------------
#define U7 8
__global__ void k7_chscan(const float* __restrict__ Alc, const float* __restrict__ Dsc){
    int cb = blockIdx.x % 8;
    int b  = blockIdx.x / 8;
    int warp = threadIdx.x>>5, lane=threadIdx.x&31;
    int il = lane>>3, j=lane&7;
    int ch = cb*16 + warp*4 + il;
    float a0 = -__expf(Alc[ch*NS + 2*j]);
    float a1 = -__expf(Alc[ch*NS + 2*j+1]);
    float Dv = Dsc[ch];
    const float* dtp  = g_dtc + ((size_t)b*DP+ch)*CI;
    const float* up   = g_xd  + ((size_t)b*DP+ch)*CI;
    const float4* bp  = g_BCc + (size_t)b*CI*8 + j;
    float* yp = g_yc + ((size_t)b*DP+ch)*CI;
    float h0=0.f, h1=0.f;
    float db[U7], ub[U7]; float4 gb[U7];
    #pragma unroll
    for (int i=0;i<U7;i++){ db[i]=dtp[i]; ub[i]=up[i]; gb[i]=bp[(size_t)i*8]; }
    for (int t0=0; t0<CI; t0+=U7){
        float yv[U7], uc[U7];
        int tn = t0 + U7;
        #pragma unroll
        for (int i=0;i<U7;i++){
            float dt=db[i], u=ub[i]; float4 g=gb[i];
            uc[i]=u;
            if (tn < CI){ db[i]=dtp[tn+i]; ub[i]=up[tn+i]; gb[i]=bp[(size_t)(tn+i)*8]; }
            float du = dt*u;
            h0 = h0*__expf(dt*a0) + du*g.x;
            h1 = h1*__expf(dt*a1) + du*g.z;
            yv[i] = h0*g.y + h1*g.w;
        }
        #pragma unroll
        for (int i=0;i<U7;i++) yv[i] += __shfl_xor_sync(0xffffffffu,yv[i],1);
        #pragma unroll
        for (int i=0;i<U7;i++) yv[i] += __shfl_xor_sync(0xffffffffu,yv[i],2);
        #pragma unroll
        for (int i=0;i<U7;i++) yv[i] += __shfl_xor_sync(0xffffffffu,yv[i],4);
        if (j==0){
            #pragma unroll
            for (int i=0;i<U7;i++) yp[t0+i] = yv[i] + Dv*uc[i];
        }
    }
}

// ---------------- K8: channel up-proj, add into ysum ----------------
__global__ void k8_up(const float* __restrict__ upw, const float* __restrict__ upb){
    int lt = blockIdx.x & 127;
    int b  = blockIdx.x >> 7;
    int l0 = lt*16;
    __shared__ float ws[16][DP];
    for (int i=threadIdx.x;i<16*DP;i+=192)
        ((float*)ws)[i] = upw[(size_t)l0*DP + i];
    __syncthreads();
    int c = threadIdx.x;
    float acc[16];
    #pragma unroll
    for (int i=0;i<16;i++) acc[i]=0.f;
    const float* yb = g_yc + (size_t)b*DP*CI + c;
    for (int ch=0;ch<DP;ch++){
        float yv = yb[(size_t)ch*CI];
        #pragma unroll
        for (int i=0;i<16;i++) acc[i] = fmaf(yv, ws[i][ch], acc[i]);
    }
    #pragma unroll
    for (int i=0;i<16;i++){
        size_t idx = ((size_t)b*L_ + l0+i)*CI + c;
        g_ysum[idx] += acc[i] + upb[l0+i];
    }
}

// ---------------- K9: LayerNorm + gate + out_proj (16 rows/block, smem W) ----------------
__global__ void __launch_bounds__(192) k9_final(const float* __restrict__ nw, const float* __restrict__ nb,
                         float* __restrict__ out){
    extern __shared__ __align__(16) float sm9[];
    float* ws   = sm9;            // [cc][m] 192*96
    float* gbuf = ws + CI*CM;     // [r][c] 16*192
    __shared__ float red[6];
    int b  = blockIdx.x >> 7;
    int l0 = (blockIdx.x & 127) << 4;
    int tid = threadIdx.x;
    for (int i=tid; i<CI*CM; i+=192) ws[i] = g_WoutT[i];
    int warp = tid>>5, lane = tid&31;
    float nwv = nw[tid], nbv = nb[tid];
    for (int r=0;r<16;r++){
        size_t base = ((size_t)b*L_ + l0 + r)*CI;
        float y = g_ysum[base + tid];
        float s = y;
        #pragma unroll
        for (int o=16;o>0;o>>=1) s += __shfl_xor_sync(0xffffffffu,s,o);
        if (lane==0) red[warp]=s;
        __syncthreads();
        float mu = (red[0]+red[1]+red[2]+red[3]+red[4]+red[5]) * (1.f/CI);
        float d = y - mu;
        float s2 = d*d;
        #pragma unroll
        for (int o=16;o>0;o>>=1) s2 += __shfl_xor_sync(0xffffffffu,s2,o);
        __syncthreads();
        if (lane==0) red[warp]=s2;
        __syncthreads();
        float var = (red[0]+red[1]+red[2]+red[3]+red[4]+red[5]) * (1.f/CI);
        float rstd = rsqrtf(var + 1e-5f);
        float yn = d*rstd*nwv + nbv;
        gbuf[r*CI + tid] = yn * g_z[base + tid];
        __syncthreads();
    }
    // GEMM 16 x 96 from smem
    int m = tid % CM, rq = tid / CM;   // rq 0/1
    for (int r = rq; r < 16; r += 2){
        const float* gr = gbuf + r*CI;
        float acc = 0.f;
        #pragma unroll 4
        for (int cc=0; cc<CI; cc++)
            acc = fmaf(gr[cc], ws[cc*CM + m], acc);
        out[((size_t)b*L_ + l0 + r)*CM + m] = acc;
    }
}

// ---------------- launch ----------------
extern "C" void kernel_launch(void* const* d_in, const int* in_sizes, int n_in,
                              void* d_out, int out_size){
    (void)in_sizes; (void)n_in; (void)out_size;
    const float* x    = (const float*)d_in[0];
    const float* inw  = (const float*)d_in[1];
    const float* convw= (const float*)d_in[2];
    const float* convb= (const float*)d_in[3];
    const float* xpw  = (const float*)d_in[4];
    const float* dtw  = (const float*)d_in[5];
    const float* dtb  = (const float*)d_in[6];
    const float* Alogs= (const float*)d_in[7];
    const float* Ds   = (const float*)d_in[8];
    const float* xpcw = (const float*)d_in[9];
    const float* dtcw = (const float*)d_in[10];
    const float* dtcb = (const float*)d_in[11];
    const float* Alc  = (const float*)d_in[12];
    const float* Dsc  = (const float*)d_in[13];
    const float* dww  = (const float*)d_in[14];
    const float* dwb  = (const float*)d_in[15];
    const float* upw  = (const float*)d_in[16];
    const float* upb  = (const float*)d_in[17];
    const float* nw   = (const float*)d_in[18];
    const float* nb   = (const float*)d_in[19];
    const float* outw = (const float*)d_in[20];
    float* out = (float*)d_out;

    int smem3 = (192*40 + 192*6 + 192 + SUBT*XR + SUBT*40) * (int)sizeof(float);
    int smem9 = (CI*CM + 16*CI) * (int)sizeof(float);
    cudaFuncSetAttribute(k3_proj,  cudaFuncAttributeMaxDynamicSharedMemorySize, smem3);
    cudaFuncSetAttribute(k9_final, cudaFuncAttributeMaxDynamicSharedMemorySize, smem9);

    k_prep    <<<128, 256>>>(inw, convw, Ds, dwb, outw);
    k1_inproj <<<B_*128, 384>>>(x);
    k2_conv   <<<B_*L_, CI>>>(convb);
    k3_proj   <<<B_*KG*16, 256, smem3>>>(xpw, dtw, dtb);
    k4_scan   <<<B_*KG*6, 256>>>(Alogs);
    k4b_merge <<<B_*L_, CI>>>();
    k5_down   <<<256, 192>>>(dww);
    k6_chproj <<<B_*CI, 128>>>(xpcw, dtcw, dtcb);
    k7_chscan <<<B_*8, 128>>>(Alc, Dsc);
    k8_up     <<<B_*128, 192>>>(upw, upb);
    k9_final  <<<B_*128, 192, smem9>>>(nw, nb, out);
}

// round 9
// speedup vs baseline: 3.9123x; 1.0300x over previous
#include <cuda_runtime.h>
#include <cuda_bf16.h>
#include <math.h>

#define B_ 2
#define L_ 2048
#define CM 96
#define CI 192
#define NS 16
#define KG 12
#define DP 128

// ---------------- scratch (device globals, no allocation) ----------------
__device__ float  g_xin[B_*L_*CI];      // [b][l][c] pre-conv
__device__ float  g_z[B_*L_*CI];        // [b][l][c] silu(z)
__device__ float  g_xc[B_*L_*CI];       // [b][l][c] post conv+silu
__device__ float  g_ysum[B_*L_*CI];     // [b][F][c] accumulated y
__device__ float  g_ybuf[B_*KG*L_*CI];  // [b][k][F][c] per-direction scan out
__device__ float  g_WinT[CM*2*CI];      // [j][o]
__device__ float  g_WoutT[CI*CM];       // [c][m]
__device__ float  g_convWT[27*CI];      // [tap][c]
__device__ int    g_src[KG*L_];         // scan index t -> gather spatial pos
__device__ int    g_tinv[KG*L_];        // spatial pos -> scan index t
__device__ int    g_dst[KG*L_];         // scan index t -> scatter flat pos
__device__ float  g_Dsum[CI];
__device__ float  g_D3[CI];
__device__ float  g_D4[CI];
__device__ float2 g_dtdu[B_*KG*L_*CI];  // [b][k][t][c] {dt, dt*u}
__device__ float4 g_BC[B_*KG*L_*8];     // [b][k][t][j] {B2j,C2j,B2j+1,C2j+1}
__device__ float  g_xd[B_*DP*CI];       // [b][p][t]
__device__ float  g_dtc[B_*DP*CI];      // [b][ch][t]
__device__ float4 g_BCc[B_*CI*8];       // [b][t][j]
__device__ float  g_yc[B_*DP*CI];       // [b][ch][t]

__device__ __forceinline__ float softplusf(float x){
    return (x > 15.f) ? x : __logf(1.f + __expf(x));
}
__device__ __forceinline__ float siluf(float x){
    return x / (1.f + __expf(-x));
}

// ---------------- prep: tables, transposes, inits ----------------
__global__ void k_prep(const float* __restrict__ inw, const float* __restrict__ convw,
                       const float* __restrict__ Ds, const float* __restrict__ downb,
                       const float* __restrict__ outw){
    int i0 = blockIdx.x*blockDim.x + threadIdx.x;
    int T  = gridDim.x*blockDim.x;
    for (int i=i0; i<CM*2*CI; i+=T){ int j=i/(2*CI), o=i%(2*CI); g_WinT[i]=inw[o*CM+j]; }
    for (int i=i0; i<CI*CM;   i+=T){ int c=i/CM,     m=i%CM;     g_WoutT[i]=outw[m*CI+c]; }
    for (int i=i0; i<27*CI;   i+=T){ int tap=i/CI,   c=i%CI;     g_convWT[i]=convw[c*27+tap]; }
    for (int i=i0; i<KG*L_;   i+=T){
        int k=i/L_, t=i%L_;
        int tt = (k>=6) ? (L_-1-t) : t;
        int h,w,d,F;
        switch(k%6){
            case 0: h=tt>>7; w=(tt>>3)&15; d=tt&7;  F=(h*16+w)*8+d;  break;
            case 1: h=tt>>7; d=(tt>>4)&7;  w=tt&15; F=(h*16+w)*8+d;  break;
            case 2: w=tt>>7; h=(tt>>3)&15; d=tt&7;  F=(h*16+w)*8+d;  break;
            case 3: w=tt>>7; d=(tt>>4)&7;  h=tt&15; F=d*256+h*16+w;  break;
            case 4: d=tt>>8; h=(tt>>4)&15; w=tt&15; F=w*128+d*16+h;  break;
            default:d=tt>>8; w=(tt>>4)&15; h=tt&15; F=(h*16+w)*8+d;  break;
        }
        int src = (h*16+w)*8+d;
        g_src[i] = src;
        g_dst[i] = F;
        g_tinv[k*L_ + src] = t;
    }
    for (int i=i0; i<CI; i+=T){
        float sa=0.f, s3=0.f, s4=0.f;
        #pragma unroll
        for (int k=0;k<KG;k++){
            float v = Ds[k*CI+i];
            int km = k%6;
            if (km==3) s3 += v;
            else if (km==4) s4 += v;
            else sa += v;
        }
        g_Dsum[i]=sa; g_D3[i]=s3; g_D4[i]=s4;
    }
    for (int i=i0; i<B_*DP*CI; i+=T){
        int p=(i/CI)%DP;
        g_xd[i]=downb[p];
    }
}

// ---------------- K1: in_proj GEMM, split xin / silu(z) ----------------
__global__ void k1_inproj(const float* __restrict__ x){
    int b  = blockIdx.x >> 7;
    int l0 = (blockIdx.x & 127) << 4;
    __shared__ __align__(16) float xs[16][CM];
    const float* src = x + ((size_t)b*L_ + l0)*CM;
    for (int i=threadIdx.x; i<16*CM; i+=384) ((float*)xs)[i] = src[i];
    __syncthreads();
    int o = threadIdx.x;
    float acc[16];
    #pragma unroll
    for (int i=0;i<16;i++) acc[i]=0.f;
    for (int j=0;j<CM;j+=4){
        float w0 = g_WinT[(j  )*(2*CI)+o];
        float w1 = g_WinT[(j+1)*(2*CI)+o];
        float w2 = g_WinT[(j+2)*(2*CI)+o];
        float w3 = g_WinT[(j+3)*(2*CI)+o];
        #pragma unroll
        for (int i=0;i<16;i++){
            float4 xv = *(const float4*)&xs[i][j];
            acc[i] = fmaf(w0,xv.x, fmaf(w1,xv.y, fmaf(w2,xv.z, fmaf(w3,xv.w, acc[i]))));
        }
    }
    if (o < CI){
        #pragma unroll
        for (int i=0;i<16;i++) g_xin[((size_t)b*L_+l0+i)*CI + o] = acc[i];
    } else {
        int c = o - CI;
        #pragma unroll
        for (int i=0;i<16;i++) g_z[((size_t)b*L_+l0+i)*CI + c] = siluf(acc[i]);
    }
}

// ---------------- K2: depthwise 3x3x3 conv + silu ----------------
__global__ void k2_conv(const float* __restrict__ convb){
    int b = blockIdx.x >> 11;
    int l = blockIdx.x & 2047;
    int h = l>>7, w=(l>>3)&15, d=l&7;
    int c = threadIdx.x;
    float acc = convb[c];
    const float* base = g_xin + (size_t)b*L_*CI;
    #pragma unroll
    for (int kh=0;kh<3;kh++){
        int hh=h+kh-1; if(hh<0||hh>15) continue;
        #pragma unroll
        for (int kw=0;kw<3;kw++){
            int ww=w+kw-1; if(ww<0||ww>15) continue;
            #pragma unroll
            for (int kd=0;kd<3;kd++){
                int dd=d+kd-1; if(dd<0||dd>7) continue;
                int lp=(hh*16+ww)*8+dd;
                acc = fmaf(base[(size_t)lp*CI+c], g_convWT[(kh*9+kw*3+kd)*CI+c], acc);
            }
        }
    }
    g_xc[((size_t)b*L_+l)*CI+c] = siluf(acc);
}

// ---------------- K3': spatial-order projection + dt expansion, scatter to scan order ----
// grid: B_*KG*32 blocks of 160 threads; each block: one (b,k), 64 spatial positions.
#define P3 64
__global__ void __launch_bounds__(160) k3p(const float* __restrict__ xpw,
                        const float* __restrict__ dtw,
                        const float* __restrict__ dtb){
    extern __shared__ __align__(16) float sm3[];
    float* xs   = sm3;                 // [p][q] P3 x 196 (padded)
    float* wsT  = xs  + P3*196;        // [q][o] 192 x 40
    float* wdt  = wsT + 192*40;        // [c][r] 192 x 6
    float* wdtb = wdt + 192*6;         // 192
    float* xdbl = wdtb + 192;          // [p][o] P3 x 40
    int*   tl   = (int*)(xdbl + P3*40);// [p] scan index
    int pc = blockIdx.x & 31;
    int k  = (blockIdx.x >> 5) % KG;
    int b  = blockIdx.x / (32*KG);
    int p0 = pc*P3;
    int tid = threadIdx.x;
    // stage xc chunk (contiguous!)
    {
        const float4* src4 = (const float4*)(g_xc + ((size_t)b*L_ + p0)*CI);
        for (int i=tid; i<P3*48; i+=160){
            int r=i/48, q=i%48;
            ((float4*)xs)[r*49 + q] = src4[i];
        }
    }
    // stage weights (transposed)
    for (int i=tid; i<38*CI; i+=160){
        int o=i/CI, q=i%CI;
        wsT[q*40+o] = xpw[(size_t)k*38*CI + i];
    }
    for (int i=tid; i<CI; i+=160){ wsT[i*40+38]=0.f; wsT[i*40+39]=0.f; }
    for (int i=tid; i<CI*6; i+=160) wdt[i]  = dtw[(size_t)k*CI*6 + i];
    for (int i=tid; i<CI;   i+=160) wdtb[i] = dtb[k*CI + i];
    for (int i=tid; i<P3;   i+=160) tl[i]   = g_tinv[k*L_ + p0 + i];
    __syncthreads();
    // GEMM: 4p x 4o per thread, 160 threads cover 64p x 40o
    {
        int pp = tid/10, op = tid%10;
        int pbase = pp*4;
        float4 a0=make_float4(0,0,0,0), a1=a0, a2=a0, a3=a0;
        const float4* x4 = (const float4*)xs;
        #pragma unroll 4
        for (int q=0; q<192; q+=4){
            float4 xv0 = x4[(pbase  )*49 + (q>>2)];
            float4 xv1 = x4[(pbase+1)*49 + (q>>2)];
            float4 xv2 = x4[(pbase+2)*49 + (q>>2)];
            float4 xv3 = x4[(pbase+3)*49 + (q>>2)];
            float4 w0 = *(const float4*)(wsT + (q  )*40 + 4*op);
            float4 w1 = *(const float4*)(wsT + (q+1)*40 + 4*op);
            float4 w2 = *(const float4*)(wsT + (q+2)*40 + 4*op);
            float4 w3 = *(const float4*)(wsT + (q+3)*40 + 4*op);
            a0.x=fmaf(xv0.x,w0.x,fmaf(xv0.y,w1.x,fmaf(xv0.z,w2.x,fmaf(xv0.w,w3.x,a0.x))));
            a0.y=fmaf(xv0.x,w0.y,fmaf(xv0.y,w1.y,fmaf(xv0.z,w2.y,fmaf(xv0.w,w3.y,a0.y))));
            a0.z=fmaf(xv0.x,w0.z,fmaf(xv0.y,w1.z,fmaf(xv0.z,w2.z,fmaf(xv0.w,w3.z,a0.z))));
            a0.w=fmaf(xv0.x,w0.w,fmaf(xv0.y,w1.w,fmaf(xv0.z,w2.w,fmaf(xv0.w,w3.w,a0.w))));
            a1.x=fmaf(xv1.x,w0.x,fmaf(xv1.y,w1.x,fmaf(xv1.z,w2.x,fmaf(xv1.w,w3.x,a1.x))));
            a1.y=fmaf(xv1.x,w0.y,fmaf(xv1.y,w1.y,fmaf(xv1.z,w2.y,fmaf(xv1.w,w3.y,a1.y))));
            a1.z=fmaf(xv1.x,w0.z,fmaf(xv1.y,w1.z,fmaf(xv1.z,w2.z,fmaf(xv1.w,w3.z,a1.z))));
            a1.w=fmaf(xv1.x,w0.w,fmaf(xv1.y,w1.w,fmaf(xv1.z,w2.w,fmaf(xv1.w,w3.w,a1.w))));
            a2.x=fmaf(xv2.x,w0.x,fmaf(xv2.y,w1.x,fmaf(xv2.z,w2.x,fmaf(xv2.w,w3.x,a2.x))));
            a2.y=fmaf(xv2.x,w0.y,fmaf(xv2.y,w1.y,fmaf(xv2.z,w2.y,fmaf(xv2.w,w3.y,a2.y))));
            a2.z=fmaf(xv2.x,w0.z,fmaf(xv2.y,w1.z,fmaf(xv2.z,w2.z,fmaf(xv2.w,w3.z,a2.z))));
            a2.w=fmaf(xv2.x,w0.w,fmaf(xv2.y,w1.w,fmaf(xv2.z,w2.w,fmaf(xv2.w,w3.w,a2.w))));
            a3.x=fmaf(xv3.x,w0.x,fmaf(xv3.y,w1.x,fmaf(xv3.z,w2.x,fmaf(xv3.w,w3.x,a3.x))));
            a3.y=fmaf(xv3.x,w0.y,fmaf(xv3.y,w1.y,fmaf(xv3.z,w2.y,fmaf(xv3.w,w3.y,a3.y))));
            a3.z=fmaf(xv3.x,w0.z,fmaf(xv3.y,w1.z,fmaf(xv3.z,w2.z,fmaf(xv3.w,w3.z,a3.z))));
            a3.w=fmaf(xv3.x,w0.w,fmaf(xv3.y,w1.w,fmaf(xv3.z,w2.w,fmaf(xv3.w,w3.w,a3.w))));
        }
        *(float4*)(xdbl + (pbase  )*40 + 4*op) = a0;
        *(float4*)(xdbl + (pbase+1)*40 + 4*op) = a1;
        *(float4*)(xdbl + (pbase+2)*40 + 4*op) = a2;
        *(float4*)(xdbl + (pbase+3)*40 + 4*op) = a3;
    }
    __syncthreads();
    size_t baseBK = (size_t)(b*KG+k)*L_;
    // dt expansion: 64*192 elements
    for (int i=tid; i<P3*CI; i+=160){
        int p = i/CI, c = i%CI;
        const float* xr = xdbl + p*40;
        float raw = wdtb[c];
        #pragma unroll
        for (int r=0;r<6;r++) raw = fmaf(wdt[c*6+r], xr[r], raw);
        float dt = softplusf(raw);
        float u  = xs[p*196 + c];
        g_dtdu[(baseBK + tl[p])*CI + c] = make_float2(dt, dt*u);
    }
    // BC: 64*8 elements
    for (int i=tid; i<P3*8; i+=160){
        int p=i/8, j=i%8;
        const float* xr = xdbl + p*40;
        g_BC[(baseBK + tl[p])*8 + j] = make_float4(xr[6+2*j],  xr[22+2*j],
                                                   xr[7+2*j],  xr[23+2*j]);
    }
}

// ---------------- K4: spatial selective scan, deep prefetch, no atomics ----------------
#define U4 16
__global__ void __launch_bounds__(256) k4_scan(const float* __restrict__ Alogs){
    int cg = blockIdx.x % 6;
    int k  = (blockIdx.x/6) % KG;
    int b  = blockIdx.x/(6*KG);
    __shared__ int pos_s[L_];
    for (int i=threadIdx.x;i<L_;i+=256) pos_s[i]=g_dst[k*L_+i];
    int warp = threadIdx.x>>5;
    int lane = threadIdx.x&31;
    int il = lane>>3, j = lane&7;
    int c = cg*32 + warp*4 + il;
    float a0 = -__expf(Alogs[(size_t)(k*CI+c)*NS + 2*j]);
    float a1 = -__expf(Alogs[(size_t)(k*CI+c)*NS + 2*j+1]);
    __syncthreads();
    const float2* dp = g_dtdu + (size_t)(b*KG+k)*L_*CI + c;
    const float4* bp = g_BC   + (size_t)(b*KG+k)*L_*8  + j;
    float* yb = g_ybuf + (size_t)(b*KG+k)*L_*CI + c;
    float h0=0.f, h1=0.f;
    float2 fb[U4]; float4 gb[U4];
    #pragma unroll
    for (int i=0;i<U4;i++){ fb[i]=dp[(size_t)i*CI]; gb[i]=bp[(size_t)i*8]; }
    for (int t0=0; t0<L_; t0+=U4){
        float yv[U4];
        int tn = t0 + U4;
        #pragma unroll
        for (int i=0;i<U4;i++){
            float2 fc = fb[i]; float4 gc = gb[i];
            if (tn < L_){
                fb[i]=dp[(size_t)(tn+i)*CI];
                gb[i]=bp[(size_t)(tn+i)*8];
            }
            float dA0 = __expf(fc.x*a0);
            float dA1 = __expf(fc.x*a1);
            h0 = h0*dA0 + fc.y*gc.x;
            h1 = h1*dA1 + fc.y*gc.z;
            yv[i] = h0*gc.y + h1*gc.w;
        }
        #pragma unroll
        for (int i=0;i<U4;i++) yv[i] += __shfl_xor_sync(0xffffffffu, yv[i], 1);
        #pragma unroll
        for (int i=0;i<U4;i++) yv[i] += __shfl_xor_sync(0xffffffffu, yv[i], 2);
        #pragma unroll
        for (int i=0;i<U4;i++) yv[i] += __shfl_xor_sync(0xffffffffu, yv[i], 4);
        if (j==0){
            #pragma unroll
            for (int i=0;i<U4;i++)
                yb[(size_t)pos_s[t0+i]*CI] = yv[i];
        }
    }
}

// ---------------- K4b: merge 12 direction outputs + all D*u terms ----------------
__global__ void k4b_merge(){
    int b = blockIdx.x >> 11;
    int F = blockIdx.x & 2047;
    int c = threadIdx.x;
    int d3 = F>>8, h3 = (F>>4)&15, w3 = F&15;
    int S3 = (h3*16+w3)*8 + d3;
    int w4 = F>>7, d4 = (F>>4)&7, h4 = F&15;
    int S4 = (h4*16+w4)*8 + d4;
    const float* xcb = g_xc + (size_t)b*L_*CI + c;
    float s = g_Dsum[c]*xcb[(size_t)F*CI]
            + g_D3[c]*xcb[(size_t)S3*CI]
            + g_D4[c]*xcb[(size_t)S4*CI];
    const float* yb = g_ybuf + ((size_t)b*KG*L_ + F)*CI + c;
    #pragma unroll
    for (int k=0;k<KG;k++) s += yb[(size_t)k*L_*CI];
    g_ysum[((size_t)b*L_+F)*CI + c] = s;
}

// ---------------- K5: channel down-proj ----------------
__global__ void k5_down(const float* __restrict__ dww){
    int lch = blockIdx.x & 7;
    int pt  = (blockIdx.x>>3) & 15;
    int b   = blockIdx.x>>7;
    int p0 = pt*8, l0 = lch*256;
    __shared__ float ws[8][256];
    for (int i=threadIdx.x;i<8*256;i+=192){
        int pi=i>>8, li=i&255;
        ws[pi][li] = dww[(size_t)(p0+pi)*L_ + l0+li];
    }
    __syncthreads();
    int c = threadIdx.x;
    float acc[8] = {0,0,0,0,0,0,0,0};
    const float* xb = g_xc + ((size_t)b*L_ + l0)*CI + c;
    for (int li=0;li<256;li++){
        float xv = xb[(size_t)li*CI];
        #pragma unroll
        for (int pi=0;pi<8;pi++) acc[pi] = fmaf(xv, ws[pi][li], acc[pi]);
    }
    #pragma unroll
    for (int pi=0;pi<8;pi++)
        atomicAdd(&g_xd[((size_t)b*DP + p0+pi)*CI + c], acc[pi]);
}

// ---------------- K6: channel projection + softplus ----------------
__global__ void k6_chproj(const float* __restrict__ xpcw,
                          const float* __restrict__ dtcw,
                          const float* __restrict__ dtcb){
    int t = blockIdx.x % CI;
    int b = blockIdx.x / CI;
    __shared__ float col[DP];
    __shared__ float sdbl[40];
    int p = threadIdx.x;
    col[p] = g_xd[((size_t)b*DP + p)*CI + t];
    __syncthreads();
    if (p < 40){
        float acc=0.f;
        for (int q=0;q<DP;q++) acc = fmaf(xpcw[(size_t)p*DP+q], col[q], acc);
        sdbl[p]=acc;
    }
    __syncthreads();
    {
        float raw = dtcb[p];
        #pragma unroll
        for (int r=0;r<8;r++) raw = fmaf(dtcw[p*8+r], sdbl[r], raw);
        g_dtc[((size_t)b*DP+p)*CI + t] = softplusf(raw);
    }
    if (p < 8){
        g_BCc[((size_t)b*CI + t)*8 + p] = make_float4(sdbl[8+2*p],  sdbl[24+2*p],
                                                      sdbl[9+2*p],  sdbl[25+2*p]);
    }
}

// ---------------- K7: channel selective scan ----------------
#define U7 8
__global__ void k7_chscan(const float* __restrict__ Alc, const float* __restrict__ Dsc){
    int cb = blockIdx.x % 8;
    int b  = blockIdx.x / 8;
    int warp = threadIdx.x>>5, lane=threadIdx.x&31;
    int il = lane>>3, j=lane&7;
    int ch = cb*16 + warp*4 + il;
    float a0 = -__expf(Alc[ch*NS + 2*j]);
    float a1 = -__expf(Alc[ch*NS + 2*j+1]);
    float Dv = Dsc[ch];
    const float* dtp  = g_dtc + ((size_t)b*DP+ch)*CI;
    const float* up   = g_xd  + ((size_t)b*DP+ch)*CI;
    const float4* bp  = g_BCc + (size_t)b*CI*8 + j;
    float* yp = g_yc + ((size_t)b*DP+ch)*CI;
    float h0=0.f, h1=0.f;
    float db[U7], ub[U7]; float4 gb[U7];
    #pragma unroll
    for (int i=0;i<U7;i++){ db[i]=dtp[i]; ub[i]=up[i]; gb[i]=bp[(size_t)i*8]; }
    for (int t0=0; t0<CI; t0+=U7){
        float yv[U7], uc[U7];
        int tn = t0 + U7;
        #pragma unroll
        for (int i=0;i<U7;i++){
            float dt=db[i], u=ub[i]; float4 g=gb[i];
            uc[i]=u;
            if (tn < CI){ db[i]=dtp[tn+i]; ub[i]=up[tn+i]; gb[i]=bp[(size_t)(tn+i)*8]; }
            float du = dt*u;
            h0 = h0*__expf(dt*a0) + du*g.x;
            h1 = h1*__expf(dt*a1) + du*g.z;
            yv[i] = h0*g.y + h1*g.w;
        }
        #pragma unroll
        for (int i=0;i<U7;i++) yv[i] += __shfl_xor_sync(0xffffffffu,yv[i],1);
        #pragma unroll
        for (int i=0;i<U7;i++) yv[i] += __shfl_xor_sync(0xffffffffu,yv[i],2);
        #pragma unroll
        for (int i=0;i<U7;i++) yv[i] += __shfl_xor_sync(0xffffffffu,yv[i],4);
        if (j==0){
            #pragma unroll
            for (int i=0;i<U7;i++) yp[t0+i] = yv[i] + Dv*uc[i];
        }
    }
}

// ---------------- K8: channel up-proj, add into ysum ----------------
__global__ void k8_up(const float* __restrict__ upw, const float* __restrict__ upb){
    int lt = blockIdx.x & 127;
    int b  = blockIdx.x >> 7;
    int l0 = lt*16;
    __shared__ float ws[16][DP];
    for (int i=threadIdx.x;i<16*DP;i+=192)
        ((float*)ws)[i] = upw[(size_t)l0*DP + i];
    __syncthreads();
    int c = threadIdx.x;
    float acc[16];
    #pragma unroll
    for (int i=0;i<16;i++) acc[i]=0.f;
    const float* yb = g_yc + (size_t)b*DP*CI + c;
    for (int ch=0;ch<DP;ch++){
        float yv = yb[(size_t)ch*CI];
        #pragma unroll
        for (int i=0;i<16;i++) acc[i] = fmaf(yv, ws[i][ch], acc[i]);
    }
    #pragma unroll
    for (int i=0;i<16;i++){
        size_t idx = ((size_t)b*L_ + l0+i)*CI + c;
        g_ysum[idx] += acc[i] + upb[l0+i];
    }
}

// ---------------- K9: LayerNorm + gate + out_proj (16 rows/block, smem W) ----------------
__global__ void __launch_bounds__(192) k9_final(const float* __restrict__ nw, const float* __restrict__ nb,
                         float* __restrict__ out){
    extern __shared__ __align__(16) float sm9[];
    float* ws   = sm9;            // [cc][m] 192*96
    float* gbuf = ws + CI*CM;     // [r][c] 16*192
    __shared__ float red[6];
    int b  = blockIdx.x >> 7;
    int l0 = (blockIdx.x & 127) << 4;
    int tid = threadIdx.x;
    for (int i=tid; i<CI*CM; i+=192) ws[i] = g_WoutT[i];
    int warp = tid>>5, lane = tid&31;
    float nwv = nw[tid], nbv = nb[tid];
    for (int r=0;r<16;r++){
        size_t base = ((size_t)b*L_ + l0 + r)*CI;
        float y = g_ysum[base + tid];
        float s = y;
        #pragma unroll
        for (int o=16;o>0;o>>=1) s += __shfl_xor_sync(0xffffffffu,s,o);
        if (lane==0) red[warp]=s;
        __syncthreads();
        float mu = (red[0]+red[1]+red[2]+red[3]+red[4]+red[5]) * (1.f/CI);
        float d = y - mu;
        float s2 = d*d;
        #pragma unroll
        for (int o=16;o>0;o>>=1) s2 += __shfl_xor_sync(0xffffffffu,s2,o);
        __syncthreads();
        if (lane==0) red[warp]=s2;
        __syncthreads();
        float var = (red[0]+red[1]+red[2]+red[3]+red[4]+red[5]) * (1.f/CI);
        float rstd = rsqrtf(var + 1e-5f);
        float yn = d*rstd*nwv + nbv;
        gbuf[r*CI + tid] = yn * g_z[base + tid];
        __syncthreads();
    }
    int m = tid % CM, rq = tid / CM;
    for (int r = rq; r < 16; r += 2){
        const float* gr = gbuf + r*CI;
        float acc = 0.f;
        #pragma unroll 4
        for (int cc=0; cc<CI; cc++)
            acc = fmaf(gr[cc], ws[cc*CM + m], acc);
        out[((size_t)b*L_ + l0 + r)*CM + m] = acc;
    }
}

// ---------------- launch ----------------
extern "C" void kernel_launch(void* const* d_in, const int* in_sizes, int n_in,
                              void* d_out, int out_size){
    (void)in_sizes; (void)n_in; (void)out_size;
    const float* x    = (const float*)d_in[0];
    const float* inw  = (const float*)d_in[1];
    const float* convw= (const float*)d_in[2];
    const float* convb= (const float*)d_in[3];
    const float* xpw  = (const float*)d_in[4];
    const float* dtw  = (const float*)d_in[5];
    const float* dtb  = (const float*)d_in[6];
    const float* Alogs= (const float*)d_in[7];
    const float* Ds   = (const float*)d_in[8];
    const float* xpcw = (const float*)d_in[9];
    const float* dtcw = (const float*)d_in[10];
    const float* dtcb = (const float*)d_in[11];
    const float* Alc  = (const float*)d_in[12];
    const float* Dsc  = (const float*)d_in[13];
    const float* dww  = (const float*)d_in[14];
    const float* dwb  = (const float*)d_in[15];
    const float* upw  = (const float*)d_in[16];
    const float* upb  = (const float*)d_in[17];
    const float* nw   = (const float*)d_in[18];
    const float* nb   = (const float*)d_in[19];
    const float* outw = (const float*)d_in[20];
    float* out = (float*)d_out;

    int smem3 = (P3*196 + 192*40 + 192*6 + 192 + P3*40) * (int)sizeof(float) + P3*(int)sizeof(int);
    int smem9 = (CI*CM + 16*CI) * (int)sizeof(float);
    cudaFuncSetAttribute(k3p,      cudaFuncAttributeMaxDynamicSharedMemorySize, smem3);
    cudaFuncSetAttribute(k9_final, cudaFuncAttributeMaxDynamicSharedMemorySize, smem9);

    k_prep    <<<128, 256>>>(inw, convw, Ds, dwb, outw);
    k1_inproj <<<B_*128, 384>>>(x);
    k2_conv   <<<B_*L_, CI>>>(convb);
    k3p       <<<B_*KG*32, 160, smem3>>>(xpw, dtw, dtb);
    k4_scan   <<<B_*KG*6, 256>>>(Alogs);
    k4b_merge <<<B_*L_, CI>>>();
    k5_down   <<<256, 192>>>(dww);
    k6_chproj <<<B_*CI, 128>>>(xpcw, dtcw, dtcb);
    k7_chscan <<<B_*8, 128>>>(Alc, Dsc);
    k8_up     <<<B_*128, 192>>>(upw, upb);
    k9_final  <<<B_*128, 192, smem9>>>(nw, nb, out);
}